// round 1
// baseline (speedup 1.0000x reference)
#include <cuda_runtime.h>
#include <math.h>

#define V_ 32000
#define E_ 1024
#define U_ 1024
#define B_ 64
#define S_ 1024

// Scratch: gate tables over the vocab (gather commutes with the GEMM),
// and the scan result h. __device__ globals per harness rules.
__device__ float g_fn[V_ * U_];   // normalized forget gate per (token, u)   ~131 MB
__device__ float g_g [V_ * U_];   // i_n * h_tilde per (token, u)            ~131 MB
__device__ float g_h [B_ * U_];   // scan output h per (b, u)

// ---------------------------------------------------------------------------
// Kernel 1: fused triple GEMM over vocab + gate epilogue.
//   For each (v, u): zf = emb[v,:]·Wf[:,u] + bf[u]  (same for i, h)
//   f = sigmoid(zf), i = sigmoid(zi), ht = zh
//   g_fn = f/(f+i);  g_g = i/(f+i) * ht
// Tile: BM=128 (vocab rows), BN=64 (u), BK=16. 256 threads, 8x4 micro-tile
// per output, 3 accumulator sets (A tile loaded once, reused for 3 B mats).
// ---------------------------------------------------------------------------
__global__ __launch_bounds__(256) void gates_gemm(
    const float* __restrict__ emb,
    const float* __restrict__ Wf, const float* __restrict__ bf,
    const float* __restrict__ Wi, const float* __restrict__ bi,
    const float* __restrict__ Wh, const float* __restrict__ bh)
{
    const int BK = 16;
    __shared__ float As[BK][132];      // A tile transposed [k][m], padded
    __shared__ float Bs[3][BK][68];    // [mat][k][n], padded

    const int m0  = blockIdx.y * 128;
    const int n0  = blockIdx.x * 64;
    const int tid = threadIdx.x;
    const int tx  = tid & 15;          // n direction (16 * 4 = 64)
    const int ty  = tid >> 4;          // m direction (16 * 8 = 128)

    float accF[8][4]; float accI[8][4]; float accH[8][4];
    #pragma unroll
    for (int i = 0; i < 8; i++)
        #pragma unroll
        for (int j = 0; j < 4; j++) { accF[i][j] = 0.f; accI[i][j] = 0.f; accH[i][j] = 0.f; }

    const float* Ws0 = Wf; const float* Ws1 = Wi; const float* Ws2 = Wh;

    for (int k0 = 0; k0 < E_; k0 += BK) {
        // ---- load A tile: 128 rows x 16 k, as float4, store transposed ----
        #pragma unroll
        for (int r = 0; r < 2; r++) {
            int j  = tid + r * 256;           // 0..511 float4 index
            int m  = j >> 2;                  // 0..127
            int kq = (j & 3) * 4;             // 0,4,8,12
            float4 a = *(const float4*)(emb + (size_t)(m0 + m) * E_ + k0 + kq);
            As[kq + 0][m] = a.x;
            As[kq + 1][m] = a.y;
            As[kq + 2][m] = a.z;
            As[kq + 3][m] = a.w;
        }
        // ---- load 3 B tiles: 16 k x 64 n each ----
        {
            int k  = tid >> 4;                // 0..15
            int n4 = (tid & 15) * 4;
            *(float4*)&Bs[0][k][n4] = *(const float4*)(Ws0 + (size_t)(k0 + k) * U_ + n0 + n4);
            *(float4*)&Bs[1][k][n4] = *(const float4*)(Ws1 + (size_t)(k0 + k) * U_ + n0 + n4);
            *(float4*)&Bs[2][k][n4] = *(const float4*)(Ws2 + (size_t)(k0 + k) * U_ + n0 + n4);
        }
        __syncthreads();

        #pragma unroll
        for (int k = 0; k < BK; k++) {
            float ra[8];
            *(float4*)&ra[0] = *(const float4*)&As[k][ty * 8];
            *(float4*)&ra[4] = *(const float4*)&As[k][ty * 8 + 4];
            float rf[4], ri[4], rh[4];
            *(float4*)rf = *(const float4*)&Bs[0][k][tx * 4];
            *(float4*)ri = *(const float4*)&Bs[1][k][tx * 4];
            *(float4*)rh = *(const float4*)&Bs[2][k][tx * 4];
            #pragma unroll
            for (int i = 0; i < 8; i++) {
                #pragma unroll
                for (int j = 0; j < 4; j++) {
                    accF[i][j] = fmaf(ra[i], rf[j], accF[i][j]);
                    accI[i][j] = fmaf(ra[i], ri[j], accI[i][j]);
                    accH[i][j] = fmaf(ra[i], rh[j], accH[i][j]);
                }
            }
        }
        __syncthreads();
    }

    // ---- epilogue: gate math, vectorized float4 stores ----
    const int nb = n0 + tx * 4;
    float bfv[4], biv[4], bhv[4];
    *(float4*)bfv = *(const float4*)(bf + nb);
    *(float4*)biv = *(const float4*)(bi + nb);
    *(float4*)bhv = *(const float4*)(bh + nb);

    #pragma unroll
    for (int i = 0; i < 8; i++) {
        size_t base = (size_t)(m0 + ty * 8 + i) * U_ + nb;
        float4 vfn, vg;
        float* pfn = (float*)&vfn;
        float* pg  = (float*)&vg;
        #pragma unroll
        for (int j = 0; j < 4; j++) {
            float f  = 1.f / (1.f + __expf(-(accF[i][j] + bfv[j])));
            float ii = 1.f / (1.f + __expf(-(accI[i][j] + biv[j])));
            float ht = accH[i][j] + bhv[j];
            float inv = 1.f / (f + ii);
            pfn[j] = f * inv;
            pg[j]  = ii * inv * ht;
        }
        *(float4*)(g_fn + base) = vfn;
        *(float4*)(g_g  + base) = vg;
    }
}

// ---------------------------------------------------------------------------
// Kernel 2: scan over time. One thread per (b, u).
//   h = fn[tok_t, u] * h + g[tok_t, u]
// Token load is warp-uniform; table loads fully coalesced over u.
// Auto-detects int64 vs int32 sentence layout (jax may demote int64->int32).
// ---------------------------------------------------------------------------
__global__ __launch_bounds__(256) void scan_kernel(const int* __restrict__ sent32)
{
    // detect dtype: if int64 little-endian, all odd int32 words are high-words = 0
    bool is64 = true;
    #pragma unroll 4
    for (int j = 0; j < 64; j++) {
        if (__ldg(&sent32[2 * j + 1]) != 0) { is64 = false; break; }
    }

    int gid = blockIdx.x * 256 + threadIdx.x;   // 0 .. B*U-1
    int b = gid >> 10;
    int u = gid & 1023;

    float h = 0.f;
    if (is64) {
        const int* srow = sent32 + (size_t)2 * b * S_;
        #pragma unroll 4
        for (int t = 0; t < S_; t++) {
            int tok = __ldg(&srow[2 * t]);
            size_t off = (size_t)tok * U_ + u;
            h = fmaf(__ldg(&g_fn[off]), h, __ldg(&g_g[off]));
        }
    } else {
        const int* srow = sent32 + (size_t)b * S_;
        #pragma unroll 4
        for (int t = 0; t < S_; t++) {
            int tok = __ldg(&srow[t]);
            size_t off = (size_t)tok * U_ + u;
            h = fmaf(__ldg(&g_fn[off]), h, __ldg(&g_g[off]));
        }
    }
    g_h[gid] = h;
}

// ---------------------------------------------------------------------------
// Kernel 3: head. out[b] = sigmoid(h[b,:] @ (W1@W2) + b1@W2 + b2)
// One block per batch element.
// ---------------------------------------------------------------------------
__global__ __launch_bounds__(256) void head_kernel(
    const float* __restrict__ W1, const float* __restrict__ b1,
    const float* __restrict__ W2, const float* __restrict__ b2,
    float* __restrict__ out)
{
    __shared__ float w12[U_];
    __shared__ float red[256];
    const int b   = blockIdx.x;
    const int tid = threadIdx.x;

    for (int u = tid; u < U_; u += 256) {
        float s = 0.f;
        #pragma unroll
        for (int c = 0; c < 64; c++) s = fmaf(W1[u * 64 + c], W2[c], s);
        w12[u] = s;
    }
    __syncthreads();

    float p = 0.f;
    for (int u = tid; u < U_; u += 256)
        p = fmaf(g_h[(size_t)b * U_ + u], w12[u], p);
    red[tid] = p;
    __syncthreads();
    #pragma unroll
    for (int s = 128; s > 0; s >>= 1) {
        if (tid < s) red[tid] += red[tid + s];
        __syncthreads();
    }
    if (tid == 0) {
        float c = 0.f;
        #pragma unroll
        for (int j = 0; j < 64; j++) c = fmaf(b1[j], W2[j], c);
        c += b2[0];
        out[b] = 1.f / (1.f + expf(-(red[0] + c)));
    }
}

// ---------------------------------------------------------------------------
extern "C" void kernel_launch(void* const* d_in, const int* in_sizes, int n_in,
                              void* d_out, int out_size)
{
    const int*   sent = (const int*)  d_in[0];   // int32 or int64 (auto-detected)
    const float* emb  = (const float*)d_in[1];
    const float* Wf   = (const float*)d_in[2];
    const float* bf   = (const float*)d_in[3];
    const float* Wi   = (const float*)d_in[4];
    const float* bi   = (const float*)d_in[5];
    const float* Wh   = (const float*)d_in[6];
    const float* bh   = (const float*)d_in[7];
    const float* W1   = (const float*)d_in[8];
    const float* b1   = (const float*)d_in[9];
    const float* W2   = (const float*)d_in[10];
    const float* b2   = (const float*)d_in[11];
    float* out = (float*)d_out;

    dim3 g1(U_ / 64, V_ / 128);     // (16, 250)
    gates_gemm<<<g1, 256>>>(emb, Wf, bf, Wi, bi, Wh, bh);
    scan_kernel<<<(B_ * U_) / 256, 256>>>(sent);
    head_kernel<<<B_, 256>>>(W1, b1, W2, b2, out);
}

// round 3
// speedup vs baseline: 2.0311x; 2.0311x over previous
#include <cuda_runtime.h>
#include <cuda_bf16.h>
#include <math.h>
#include <stdint.h>

#define V_ 32000
#define E_ 1024
#define U_ 1024
#define B_ 64
#define S_ 1024

#define BM 128
#define BN 64
#define BK 32
#define NKT (E_ / BK)            // 32 k-tiles
#define SROW 40                  // padded row stride (bf16 elems) = 80 bytes
#define A_TILE (BM * SROW * 2)   // 10240 B
#define B_TILE (BN * SROW * 2)   // 5120 B
#define STAGE_BYTES (2 * A_TILE + 6 * B_TILE)   // 51200 B
#define STAGES 3
#define SMEM_DYN (STAGES * STAGE_BYTES)         // 153600 B

// ---------------- device scratch (__device__ globals; no allocs allowed) ----
__device__ float g_fn[(size_t)V_ * U_];
__device__ float g_g [(size_t)V_ * U_];
__device__ float g_h [B_ * U_];
__device__ __nv_bfloat16 g_embhi[(size_t)V_ * E_];
__device__ __nv_bfloat16 g_emblo[(size_t)V_ * E_];
__device__ __nv_bfloat16 g_wthi[3][(size_t)U_ * E_];
__device__ __nv_bfloat16 g_wtlo[3][(size_t)U_ * E_];

// ---------------- asm helpers (base sm_103 ISA only) ------------------------
__device__ __forceinline__ uint32_t smem_u32(const void* p) {
    uint32_t a;
    asm("{ .reg .u64 t; cvta.to.shared.u64 t, %1; cvt.u32.u64 %0, t; }" : "=r"(a) : "l"(p));
    return a;
}
__device__ __forceinline__ void cp16(uint32_t dst, const void* src) {
    asm volatile("cp.async.cg.shared.global [%0], [%1], 16;" :: "r"(dst), "l"(src));
}
#define CP_COMMIT() asm volatile("cp.async.commit_group;" ::: "memory")
#define CP_WAIT(N)  asm volatile("cp.async.wait_group %0;" :: "n"(N) : "memory")

__device__ __forceinline__ void ldsm4(uint32_t* r, uint32_t addr) {
    asm volatile("ldmatrix.sync.aligned.m8n8.x4.shared.b16 {%0,%1,%2,%3}, [%4];"
        : "=r"(r[0]), "=r"(r[1]), "=r"(r[2]), "=r"(r[3]) : "r"(addr));
}
__device__ __forceinline__ void mma16816(float* c, const uint32_t* a, const uint32_t* b) {
    asm volatile(
        "mma.sync.aligned.m16n8k16.row.col.f32.bf16.bf16.f32 "
        "{%0,%1,%2,%3}, {%4,%5,%6,%7}, {%8,%9}, {%0,%1,%2,%3};"
        : "+f"(c[0]), "+f"(c[1]), "+f"(c[2]), "+f"(c[3])
        : "r"(a[0]), "r"(a[1]), "r"(a[2]), "r"(a[3]), "r"(b[0]), "r"(b[1]));
}

// ---------------- kernel 0a: split emb fp32 -> (hi, lo) bf16 ----------------
__global__ __launch_bounds__(256) void split_emb_k(const float* __restrict__ emb) {
    size_t i = (size_t)blockIdx.x * 256 + threadIdx.x;
    if (i >= (size_t)V_ * E_) return;
    float x = emb[i];
    __nv_bfloat16 h = __float2bfloat16(x);
    g_embhi[i] = h;
    g_emblo[i] = __float2bfloat16(x - __bfloat162float(h));
}

// ---------------- kernel 0b: transpose + split W[e,u] -> Wt[u,e] ------------
__global__ __launch_bounds__(256) void transpose_split_w_k(
    const float* __restrict__ Wf, const float* __restrict__ Wi, const float* __restrict__ Wh) {
    __shared__ float t[32][33];
    int mat = blockIdx.z;
    const float* W = (mat == 0) ? Wf : (mat == 1) ? Wi : Wh;
    int u0 = blockIdx.x * 32, e0 = blockIdx.y * 32;
    int tx = threadIdx.x, ty = threadIdx.y;   // block (32, 8)
    #pragma unroll
    for (int r = 0; r < 32; r += 8)
        t[ty + r][tx] = W[(size_t)(e0 + ty + r) * U_ + u0 + tx];
    __syncthreads();
    __nv_bfloat16* oh = g_wthi[mat];
    __nv_bfloat16* ol = g_wtlo[mat];
    #pragma unroll
    for (int r = 0; r < 32; r += 8) {
        float x = t[tx][ty + r];
        __nv_bfloat16 h = __float2bfloat16(x);
        size_t o = (size_t)(u0 + ty + r) * E_ + e0 + tx;
        oh[o] = h;
        ol[o] = __float2bfloat16(x - __bfloat162float(h));
    }
}

// ---------------- kernel 1: pipelined mma.sync triple GEMM + gates ----------
__global__ __launch_bounds__(256, 1) void gates_mma(
    const float* __restrict__ bfb, const float* __restrict__ bib,
    const float* __restrict__ bhb)
{
    extern __shared__ char smem[];
    const uint32_t sb = smem_u32(smem);
    const int tid  = threadIdx.x;
    const int lane = tid & 31, wid = tid >> 5;
    const int wm = wid & 3;          // 4 warps in m  (4*32 = 128)
    const int wn = wid >> 2;         // 2 warps in n  (2*32 = 64)
    const int m0 = blockIdx.y * BM, n0 = blockIdx.x * BN;

    const __nv_bfloat16* bsrc[6] = { g_wthi[0], g_wtlo[0], g_wthi[1],
                                     g_wtlo[1], g_wthi[2], g_wtlo[2] };

    float acc[3][2][4][4];
    #pragma unroll
    for (int m = 0; m < 3; m++)
        #pragma unroll
        for (int t = 0; t < 2; t++)
            #pragma unroll
            for (int j = 0; j < 4; j++)
                #pragma unroll
                for (int r = 0; r < 4; r++) acc[m][t][j][r] = 0.f;

    // ---- stage loader: 10 cp.async per thread ----
    auto load_stage = [&](int kt, int s) {
        const uint32_t base = sb + s * STAGE_BYTES;
        const int k0 = kt * BK;
        #pragma unroll
        for (int i = 0; i < 2; i++) {                 // A: 512 chunks
            int c = tid + i * 256;
            int row = c >> 2, seg = c & 3;
            size_t off = (size_t)(m0 + row) * E_ + k0 + seg * 8;
            uint32_t d = base + row * (SROW * 2) + seg * 16;
            cp16(d,          g_embhi + off);
            cp16(d + A_TILE, g_emblo + off);
        }
        {                                              // B: 6 tiles x 256 chunks
            int row = tid >> 2, seg = tid & 3;
            size_t off = (size_t)(n0 + row) * E_ + k0 + seg * 8;
            uint32_t d = base + 2 * A_TILE + row * (SROW * 2) + seg * 16;
            #pragma unroll
            for (int t = 0; t < 6; t++)
                cp16(d + t * B_TILE, bsrc[t] + off);
        }
        CP_COMMIT();
    };

    const int lq = lane >> 3, lr = lane & 7;

    load_stage(0, 0);
    load_stage(1, 1);

    for (int kt = 0; kt < NKT; ++kt) {
        if (kt < NKT - 1) { CP_WAIT(1); } else { CP_WAIT(0); }
        __syncthreads();

        const uint32_t base = sb + (kt % STAGES) * STAGE_BYTES;
        #pragma unroll
        for (int ks = 0; ks < 2; ++ks) {
            uint32_t aHi[2][4], aLo[2][4];
            #pragma unroll
            for (int t = 0; t < 2; t++) {
                int row = wm * 32 + t * 16 + (lq & 1) * 8 + lr;
                uint32_t ad = base + row * (SROW * 2) + ks * 32 + (lq >> 1) * 16;
                ldsm4(aHi[t], ad);
                ldsm4(aLo[t], ad + A_TILE);
            }
            #pragma unroll
            for (int mat = 0; mat < 3; mat++) {
                uint32_t bHi[2][4], bLo[2][4];
                #pragma unroll
                for (int jp = 0; jp < 2; jp++) {
                    int row = wn * 32 + jp * 16 + (lq >> 1) * 8 + lr;
                    uint32_t bd = base + 2 * A_TILE + (2 * mat) * B_TILE
                                + row * (SROW * 2) + ks * 32 + (lq & 1) * 16;
                    ldsm4(bHi[jp], bd);
                    ldsm4(bLo[jp], bd + B_TILE);
                }
                #pragma unroll
                for (int t = 0; t < 2; t++)
                    #pragma unroll
                    for (int j = 0; j < 4; j++) {
                        const uint32_t* bh_ = &bHi[j >> 1][(j & 1) * 2];
                        const uint32_t* bl_ = &bLo[j >> 1][(j & 1) * 2];
                        mma16816(acc[mat][t][j], aHi[t], bh_);  // hi*hi
                        mma16816(acc[mat][t][j], aHi[t], bl_);  // hi*lo
                        mma16816(acc[mat][t][j], aLo[t], bh_);  // lo*hi
                    }
            }
        }
        __syncthreads();
        if (kt + 2 < NKT) load_stage(kt + 2, (kt + 2) % STAGES);
    }

    // ---- epilogue: gate math + float2 stores ----
    #pragma unroll
    for (int j = 0; j < 4; j++) {
        int col = n0 + wn * 32 + j * 8 + (lane & 3) * 2;
        float2 bfv = *(const float2*)(bfb + col);
        float2 biv = *(const float2*)(bib + col);
        float2 bhv = *(const float2*)(bhb + col);
        #pragma unroll
        for (int t = 0; t < 2; t++) {
            #pragma unroll
            for (int rh = 0; rh < 2; rh++) {
                int row = m0 + wm * 32 + t * 16 + (lane >> 2) + rh * 8;
                float zf0 = acc[0][t][j][rh * 2 + 0] + bfv.x;
                float zf1 = acc[0][t][j][rh * 2 + 1] + bfv.y;
                float zi0 = acc[1][t][j][rh * 2 + 0] + biv.x;
                float zi1 = acc[1][t][j][rh * 2 + 1] + biv.y;
                float zh0 = acc[2][t][j][rh * 2 + 0] + bhv.x;
                float zh1 = acc[2][t][j][rh * 2 + 1] + bhv.y;
                float f0 = 1.f / (1.f + __expf(-zf0));
                float f1 = 1.f / (1.f + __expf(-zf1));
                float i0 = 1.f / (1.f + __expf(-zi0));
                float i1 = 1.f / (1.f + __expf(-zi1));
                float v0 = 1.f / (f0 + i0);
                float v1 = 1.f / (f1 + i1);
                size_t ga = (size_t)row * U_ + col;
                *(float2*)(g_fn + ga) = make_float2(f0 * v0, f1 * v1);
                *(float2*)(g_g  + ga) = make_float2(i0 * v0 * zh0, i1 * v1 * zh1);
            }
        }
    }
}

// ---------------- kernel 2: sequential scan over time -----------------------
__global__ __launch_bounds__(256) void scan_kernel(const int* __restrict__ sent32)
{
    bool is64 = true;
    #pragma unroll 4
    for (int j = 0; j < 64; j++)
        if (__ldg(&sent32[2 * j + 1]) != 0) { is64 = false; break; }

    int gid = blockIdx.x * 256 + threadIdx.x;
    int b = gid >> 10, u = gid & 1023;

    float h = 0.f;
    if (is64) {
        const int* srow = sent32 + (size_t)2 * b * S_;
        #pragma unroll 4
        for (int t = 0; t < S_; t++) {
            int tok = __ldg(&srow[2 * t]);
            size_t off = (size_t)tok * U_ + u;
            h = fmaf(__ldg(&g_fn[off]), h, __ldg(&g_g[off]));
        }
    } else {
        const int* srow = sent32 + (size_t)b * S_;
        #pragma unroll 4
        for (int t = 0; t < S_; t++) {
            int tok = __ldg(&srow[t]);
            size_t off = (size_t)tok * U_ + u;
            h = fmaf(__ldg(&g_fn[off]), h, __ldg(&g_g[off]));
        }
    }
    g_h[gid] = h;
}

// ---------------- kernel 3: head ---------------------------------------------
__global__ __launch_bounds__(256) void head_kernel(
    const float* __restrict__ W1, const float* __restrict__ b1,
    const float* __restrict__ W2, const float* __restrict__ b2,
    float* __restrict__ out)
{
    __shared__ float w12[U_];
    __shared__ float red[256];
    const int b = blockIdx.x, tid = threadIdx.x;

    for (int u = tid; u < U_; u += 256) {
        float s = 0.f;
        #pragma unroll
        for (int c = 0; c < 64; c++) s = fmaf(W1[u * 64 + c], W2[c], s);
        w12[u] = s;
    }
    __syncthreads();
    float p = 0.f;
    for (int u = tid; u < U_; u += 256)
        p = fmaf(g_h[(size_t)b * U_ + u], w12[u], p);
    red[tid] = p;
    __syncthreads();
    #pragma unroll
    for (int s = 128; s > 0; s >>= 1) {
        if (tid < s) red[tid] += red[tid + s];
        __syncthreads();
    }
    if (tid == 0) {
        float c = 0.f;
        #pragma unroll
        for (int j = 0; j < 64; j++) c = fmaf(b1[j], W2[j], c);
        out[b] = 1.f / (1.f + expf(-(red[0] + c + b2[0])));
    }
}

// ---------------- host -------------------------------------------------------
extern "C" void kernel_launch(void* const* d_in, const int* in_sizes, int n_in,
                              void* d_out, int out_size)
{
    const int*   sent = (const int*)  d_in[0];
    const float* emb  = (const float*)d_in[1];
    const float* Wf   = (const float*)d_in[2];
    const float* bf   = (const float*)d_in[3];
    const float* Wi   = (const float*)d_in[4];
    const float* bi   = (const float*)d_in[5];
    const float* Wh   = (const float*)d_in[6];
    const float* bh   = (const float*)d_in[7];
    const float* W1   = (const float*)d_in[8];
    const float* b1   = (const float*)d_in[9];
    const float* W2   = (const float*)d_in[10];
    const float* b2   = (const float*)d_in[11];
    float* out = (float*)d_out;

    static int smem_set = 0;
    if (!smem_set) {
        cudaFuncSetAttribute(gates_mma, cudaFuncAttributeMaxDynamicSharedMemorySize, SMEM_DYN);
        smem_set = 1;
    }

    split_emb_k<<<(int)(((size_t)V_ * E_ + 255) / 256), 256>>>(emb);
    transpose_split_w_k<<<dim3(U_ / 32, E_ / 32, 3), dim3(32, 8)>>>(Wf, Wi, Wh);
    gates_mma<<<dim3(U_ / BN, V_ / BM), 256, SMEM_DYN>>>(bf, bi, bh);
    scan_kernel<<<(B_ * U_) / 256, 256>>>(sent);
    head_kernel<<<B_, 256>>>(W1, b1, W2, b2, out);
}

// round 4
// speedup vs baseline: 4.2038x; 2.0698x over previous
#include <cuda_runtime.h>
#include <cuda_fp16.h>
#include <math.h>
#include <stdint.h>

#define V_ 32000
#define E_ 1024
#define U_ 1024
#define B_ 64
#define S_ 1024

#define BM 128
#define BN 64
#define BK 32
#define NKT (E_ / BK)            // 32 k-tiles
#define SROW 40                  // padded row stride (fp16 elems) = 80 bytes
#define A_TILE (BM * SROW * 2)   // 10240 B
#define B_TILE (BN * SROW * 2)   // 5120 B
#define STAGE_BYTES (A_TILE + 3 * B_TILE)   // 25600 B
#define STAGES 4
#define SMEM_DYN (STAGES * STAGE_BYTES)     // 102400 B

#define NCH 8                    // scan chunks
#define CHL (S_ / NCH)           // 128 timesteps per chunk

// ---------------- device scratch (__device__ globals; no allocs allowed) ----
__device__ float g_fn[(size_t)V_ * U_];
__device__ float g_g [(size_t)V_ * U_];
__device__ float g_h [B_ * U_];
__device__ float g_P [NCH * B_ * U_];
__device__ float g_Q [NCH * B_ * U_];
__device__ __half g_emb[(size_t)V_ * E_];
__device__ __half g_wt[3][(size_t)U_ * E_];

// ---------------- asm helpers (base sm_103 ISA only) ------------------------
__device__ __forceinline__ uint32_t smem_u32(const void* p) {
    uint32_t a;
    asm("{ .reg .u64 t; cvta.to.shared.u64 t, %1; cvt.u32.u64 %0, t; }" : "=r"(a) : "l"(p));
    return a;
}
__device__ __forceinline__ void cp16(uint32_t dst, const void* src) {
    asm volatile("cp.async.cg.shared.global [%0], [%1], 16;" :: "r"(dst), "l"(src));
}
#define CP_COMMIT() asm volatile("cp.async.commit_group;" ::: "memory")
#define CP_WAIT(N)  asm volatile("cp.async.wait_group %0;" :: "n"(N) : "memory")

__device__ __forceinline__ void ldsm4(uint32_t* r, uint32_t addr) {
    asm volatile("ldmatrix.sync.aligned.m8n8.x4.shared.b16 {%0,%1,%2,%3}, [%4];"
        : "=r"(r[0]), "=r"(r[1]), "=r"(r[2]), "=r"(r[3]) : "r"(addr));
}
__device__ __forceinline__ void mma16816(float* c, const uint32_t* a, const uint32_t* b) {
    asm volatile(
        "mma.sync.aligned.m16n8k16.row.col.f32.f16.f16.f32 "
        "{%0,%1,%2,%3}, {%4,%5,%6,%7}, {%8,%9}, {%0,%1,%2,%3};"
        : "+f"(c[0]), "+f"(c[1]), "+f"(c[2]), "+f"(c[3])
        : "r"(a[0]), "r"(a[1]), "r"(a[2]), "r"(a[3]), "r"(b[0]), "r"(b[1]));
}

// ---------------- kernel 0a: convert emb fp32 -> fp16 ------------------------
__global__ __launch_bounds__(256) void conv_emb_k(const float* __restrict__ emb) {
    size_t i = ((size_t)blockIdx.x * 256 + threadIdx.x) * 4;
    if (i >= (size_t)V_ * E_) return;
    float4 x = *(const float4*)(emb + i);
    __half2* o = (__half2*)(g_emb + i);
    o[0] = __floats2half2_rn(x.x, x.y);
    o[1] = __floats2half2_rn(x.z, x.w);
}

// ---------------- kernel 0b: transpose W[e,u] -> Wt[u,e] fp16 ---------------
__global__ __launch_bounds__(256) void transpose_w_k(
    const float* __restrict__ Wf, const float* __restrict__ Wi, const float* __restrict__ Wh) {
    __shared__ float t[32][33];
    int mat = blockIdx.z;
    const float* W = (mat == 0) ? Wf : (mat == 1) ? Wi : Wh;
    int u0 = blockIdx.x * 32, e0 = blockIdx.y * 32;
    int tx = threadIdx.x, ty = threadIdx.y;   // block (32, 8)
    #pragma unroll
    for (int r = 0; r < 32; r += 8)
        t[ty + r][tx] = W[(size_t)(e0 + ty + r) * U_ + u0 + tx];
    __syncthreads();
    __half* oh = g_wt[mat];
    #pragma unroll
    for (int r = 0; r < 32; r += 8)
        oh[(size_t)(u0 + ty + r) * E_ + e0 + tx] = __float2half_rn(t[tx][ty + r]);
}

// ---------------- kernel 1: pipelined fp16 mma triple GEMM + gates ----------
__global__ __launch_bounds__(256, 1) void gates_mma(
    const float* __restrict__ bfb, const float* __restrict__ bib,
    const float* __restrict__ bhb)
{
    extern __shared__ char smem[];
    const uint32_t sb = smem_u32(smem);
    const int tid  = threadIdx.x;
    const int lane = tid & 31, wid = tid >> 5;
    const int wm = wid & 3;          // 4 warps in m  (4*32 = 128)
    const int wn = wid >> 2;         // 2 warps in n  (2*32 = 64)
    const int m0 = blockIdx.y * BM, n0 = blockIdx.x * BN;

    float acc[3][2][4][4];
    #pragma unroll
    for (int m = 0; m < 3; m++)
        #pragma unroll
        for (int t = 0; t < 2; t++)
            #pragma unroll
            for (int j = 0; j < 4; j++)
                #pragma unroll
                for (int r = 0; r < 4; r++) acc[m][t][j][r] = 0.f;

    // ---- stage loader: 5 cp.async per thread ----
    auto load_stage = [&](int kt, int s) {
        const uint32_t base = sb + s * STAGE_BYTES;
        const int k0 = kt * BK;
        #pragma unroll
        for (int i = 0; i < 2; i++) {                 // A: 512 chunks of 16B
            int c = tid + i * 256;
            int row = c >> 2, seg = c & 3;
            cp16(base + row * (SROW * 2) + seg * 16,
                 g_emb + (size_t)(m0 + row) * E_ + k0 + seg * 8);
        }
        {                                              // B: 3 tiles x 256 chunks
            int row = tid >> 2, seg = tid & 3;
            uint32_t d = base + A_TILE + row * (SROW * 2) + seg * 16;
            size_t off = (size_t)(n0 + row) * E_ + k0 + seg * 8;
            #pragma unroll
            for (int t = 0; t < 3; t++)
                cp16(d + t * B_TILE, g_wt[t] + off);
        }
        CP_COMMIT();
    };

    const int lq = lane >> 3, lr = lane & 7;

    load_stage(0, 0);
    load_stage(1, 1);
    load_stage(2, 2);

    for (int kt = 0; kt < NKT; ++kt) {
        if      (kt < NKT - 2) { CP_WAIT(2); }
        else if (kt < NKT - 1) { CP_WAIT(1); }
        else                   { CP_WAIT(0); }
        __syncthreads();

        const uint32_t base = sb + (kt % STAGES) * STAGE_BYTES;
        #pragma unroll
        for (int ks = 0; ks < 2; ++ks) {
            uint32_t aF[2][4];
            #pragma unroll
            for (int t = 0; t < 2; t++) {
                int row = wm * 32 + t * 16 + (lq & 1) * 8 + lr;
                ldsm4(aF[t], base + row * (SROW * 2) + ks * 32 + (lq >> 1) * 16);
            }
            #pragma unroll
            for (int mat = 0; mat < 3; mat++) {
                uint32_t bF[2][4];
                #pragma unroll
                for (int jp = 0; jp < 2; jp++) {
                    int row = wn * 32 + jp * 16 + (lq >> 1) * 8 + lr;
                    ldsm4(bF[jp], base + A_TILE + mat * B_TILE
                                + row * (SROW * 2) + ks * 32 + (lq & 1) * 16);
                }
                #pragma unroll
                for (int t = 0; t < 2; t++)
                    #pragma unroll
                    for (int j = 0; j < 4; j++)
                        mma16816(acc[mat][t][j], aF[t], &bF[j >> 1][(j & 1) * 2]);
            }
        }
        __syncthreads();
        if (kt + 3 < NKT) load_stage(kt + 3, (kt + 3) % STAGES);
    }

    // ---- epilogue: gate math + float2 stores ----
    #pragma unroll
    for (int j = 0; j < 4; j++) {
        int col = n0 + wn * 32 + j * 8 + (lane & 3) * 2;
        float2 bfv = *(const float2*)(bfb + col);
        float2 biv = *(const float2*)(bib + col);
        float2 bhv = *(const float2*)(bhb + col);
        #pragma unroll
        for (int t = 0; t < 2; t++) {
            #pragma unroll
            for (int rh = 0; rh < 2; rh++) {
                int row = m0 + wm * 32 + t * 16 + (lane >> 2) + rh * 8;
                float zf0 = acc[0][t][j][rh * 2 + 0] + bfv.x;
                float zf1 = acc[0][t][j][rh * 2 + 1] + bfv.y;
                float zi0 = acc[1][t][j][rh * 2 + 0] + biv.x;
                float zi1 = acc[1][t][j][rh * 2 + 1] + biv.y;
                float zh0 = acc[2][t][j][rh * 2 + 0] + bhv.x;
                float zh1 = acc[2][t][j][rh * 2 + 1] + bhv.y;
                float f0 = 1.f / (1.f + __expf(-zf0));
                float f1 = 1.f / (1.f + __expf(-zf1));
                float i0 = 1.f / (1.f + __expf(-zi0));
                float i1 = 1.f / (1.f + __expf(-zi1));
                float v0 = 1.f / (f0 + i0);
                float v1 = 1.f / (f1 + i1);
                size_t ga = (size_t)row * U_ + col;
                *(float2*)(g_fn + ga) = make_float2(f0 * v0, f1 * v1);
                *(float2*)(g_g  + ga) = make_float2(i0 * v0 * zh0, i1 * v1 * zh1);
            }
        }
    }
}

// ---------------- kernel 2a: chunked scan (parallel over 8 chunks) ----------
__global__ __launch_bounds__(256) void scan_part(const int* __restrict__ sent32)
{
    bool is64 = true;
    #pragma unroll 4
    for (int j = 0; j < 64; j++)
        if (__ldg(&sent32[2 * j + 1]) != 0) { is64 = false; break; }

    const int u = blockIdx.x * 256 + threadIdx.x;   // grid.x = 4
    const int b = blockIdx.y;
    const int c = blockIdx.z;
    const int t0 = c * CHL;

    float P = 1.f, h = 0.f;
    if (is64) {
        const int* srow = sent32 + (size_t)2 * (b * S_ + t0);
        #pragma unroll 4
        for (int t = 0; t < CHL; t++) {
            int tok = __ldg(&srow[2 * t]);
            size_t off = (size_t)tok * U_ + u;
            float f = __ldg(&g_fn[off]);
            float g = __ldg(&g_g[off]);
            h = fmaf(f, h, g);
            P *= f;
        }
    } else {
        const int* srow = sent32 + (size_t)(b * S_ + t0);
        #pragma unroll 4
        for (int t = 0; t < CHL; t++) {
            int tok = __ldg(&srow[t]);
            size_t off = (size_t)tok * U_ + u;
            float f = __ldg(&g_fn[off]);
            float g = __ldg(&g_g[off]);
            h = fmaf(f, h, g);
            P *= f;
        }
    }
    size_t idx = ((size_t)c * B_ + b) * U_ + u;
    g_P[idx] = P;
    g_Q[idx] = h;
}

// ---------------- kernel 2b: combine chunk results ---------------------------
__global__ __launch_bounds__(256) void scan_combine()
{
    int gid = blockIdx.x * 256 + threadIdx.x;   // 0 .. B*U-1
    int b = gid >> 10, u = gid & 1023;
    float h = 0.f;
    #pragma unroll
    for (int c = 0; c < NCH; c++) {
        size_t idx = ((size_t)c * B_ + b) * U_ + u;
        h = fmaf(g_P[idx], h, g_Q[idx]);
    }
    g_h[gid] = h;
}

// ---------------- kernel 3: head ---------------------------------------------
__global__ __launch_bounds__(256) void head_kernel(
    const float* __restrict__ W1, const float* __restrict__ b1,
    const float* __restrict__ W2, const float* __restrict__ b2,
    float* __restrict__ out)
{
    __shared__ float w12[U_];
    __shared__ float red[256];
    const int b = blockIdx.x, tid = threadIdx.x;

    for (int u = tid; u < U_; u += 256) {
        float s = 0.f;
        #pragma unroll
        for (int c = 0; c < 64; c++) s = fmaf(W1[u * 64 + c], W2[c], s);
        w12[u] = s;
    }
    __syncthreads();
    float p = 0.f;
    for (int u = tid; u < U_; u += 256)
        p = fmaf(g_h[(size_t)b * U_ + u], w12[u], p);
    red[tid] = p;
    __syncthreads();
    #pragma unroll
    for (int s = 128; s > 0; s >>= 1) {
        if (tid < s) red[tid] += red[tid + s];
        __syncthreads();
    }
    if (tid == 0) {
        float c = 0.f;
        #pragma unroll
        for (int j = 0; j < 64; j++) c = fmaf(b1[j], W2[j], c);
        out[b] = 1.f / (1.f + expf(-(red[0] + c + b2[0])));
    }
}

// ---------------- host -------------------------------------------------------
extern "C" void kernel_launch(void* const* d_in, const int* in_sizes, int n_in,
                              void* d_out, int out_size)
{
    const int*   sent = (const int*)  d_in[0];
    const float* emb  = (const float*)d_in[1];
    const float* Wf   = (const float*)d_in[2];
    const float* bf   = (const float*)d_in[3];
    const float* Wi   = (const float*)d_in[4];
    const float* bi   = (const float*)d_in[5];
    const float* Wh   = (const float*)d_in[6];
    const float* bh   = (const float*)d_in[7];
    const float* W1   = (const float*)d_in[8];
    const float* b1   = (const float*)d_in[9];
    const float* W2   = (const float*)d_in[10];
    const float* b2   = (const float*)d_in[11];
    float* out = (float*)d_out;

    cudaFuncSetAttribute(gates_mma, cudaFuncAttributeMaxDynamicSharedMemorySize, SMEM_DYN);

    conv_emb_k<<<(int)(((size_t)V_ * E_ / 4 + 255) / 256), 256>>>(emb);
    transpose_w_k<<<dim3(U_ / 32, E_ / 32, 3), dim3(32, 8)>>>(Wf, Wi, Wh);
    gates_mma<<<dim3(U_ / BN, V_ / BM), 256, SMEM_DYN>>>(bf, bi, bh);
    scan_part<<<dim3(U_ / 256, B_, NCH), 256>>>(sent);
    scan_combine<<<(B_ * U_) / 256, 256>>>();
    head_kernel<<<B_, 256>>>(W1, b1, W2, b2, out);
}

// round 5
// speedup vs baseline: 4.7377x; 1.1270x over previous
#include <cuda_runtime.h>
#include <cuda_fp16.h>
#include <math.h>
#include <stdint.h>

#define V_ 32000
#define E_ 1024
#define U_ 1024
#define B_ 64
#define S_ 1024

#define BM 128
#define BN 64
#define BK 32
#define NKT (E_ / BK)            // 32 k-tiles
#define SROW 40                  // padded row stride (fp16 elems) = 80 bytes
#define A_TILE (BM * SROW * 2)   // 10240 B
#define B_TILE (BN * SROW * 2)   // 5120 B
#define STAGE_BYTES (A_TILE + 3 * B_TILE)   // 25600 B
#define STAGES 4
#define SMEM_DYN (STAGES * STAGE_BYTES)     // 102400 B

#define NCH 16                   // scan chunks
#define CHL (S_ / NCH)           // 64 timesteps per chunk

// ---------------- device scratch (__device__ globals; no allocs allowed) ----
__device__ int     g_cnt;
__device__ int     g_remap[V_];
__device__ int     g_ulist[V_];
__device__ int     g_sent[B_ * S_];
__device__ __half2 g_tab[(size_t)V_ * U_];   // (f_n, i_n*h~) packed, row = compact id
__device__ float   g_h [B_ * U_];
__device__ float   g_P [NCH * B_ * U_];
__device__ float   g_Q [NCH * B_ * U_];
__device__ __half  g_emb[(size_t)V_ * E_];
__device__ __half  g_wt[3][(size_t)U_ * E_];

// ---------------- asm helpers (base sm_103 ISA only) ------------------------
__device__ __forceinline__ uint32_t smem_u32(const void* p) {
    uint32_t a;
    asm("{ .reg .u64 t; cvta.to.shared.u64 t, %1; cvt.u32.u64 %0, t; }" : "=r"(a) : "l"(p));
    return a;
}
__device__ __forceinline__ void cp16(uint32_t dst, const void* src) {
    asm volatile("cp.async.cg.shared.global [%0], [%1], 16;" :: "r"(dst), "l"(src));
}
#define CP_COMMIT() asm volatile("cp.async.commit_group;" ::: "memory")
#define CP_WAIT(N)  asm volatile("cp.async.wait_group %0;" :: "n"(N) : "memory")

__device__ __forceinline__ void ldsm4(uint32_t* r, uint32_t addr) {
    asm volatile("ldmatrix.sync.aligned.m8n8.x4.shared.b16 {%0,%1,%2,%3}, [%4];"
        : "=r"(r[0]), "=r"(r[1]), "=r"(r[2]), "=r"(r[3]) : "r"(addr));
}
__device__ __forceinline__ void mma16816(float* c, const uint32_t* a, const uint32_t* b) {
    asm volatile(
        "mma.sync.aligned.m16n8k16.row.col.f32.f16.f16.f32 "
        "{%0,%1,%2,%3}, {%4,%5,%6,%7}, {%8,%9}, {%0,%1,%2,%3};"
        : "+f"(c[0]), "+f"(c[1]), "+f"(c[2]), "+f"(c[3])
        : "r"(a[0]), "r"(a[1]), "r"(a[2]), "r"(a[3]), "r"(b[0]), "r"(b[1]));
}
__device__ __forceinline__ bool sent_is64(const int* __restrict__ s) {
    #pragma unroll 4
    for (int j = 0; j < 64; j++)
        if (__ldg(&s[2 * j + 1]) != 0) return false;
    return true;
}

// ---------------- kernel P0: reset remap + counter ---------------------------
__global__ __launch_bounds__(256) void zero_k() {
    int v = blockIdx.x * 256 + threadIdx.x;
    if (v < V_) g_remap[v] = -1;
    if (v == 0) g_cnt = 0;
}

// ---------------- kernel P1: mark unique tokens, build compact list ---------
__global__ __launch_bounds__(256) void mark_k(const int* __restrict__ sent32) {
    bool is64 = sent_is64(sent32);
    int i = blockIdx.x * 256 + threadIdx.x;            // 0 .. B*S-1
    int tok = is64 ? __ldg(&sent32[2 * i]) : __ldg(&sent32[i]);
    int old = atomicCAS(&g_remap[tok], -1, -2);
    if (old == -1) {
        int pos = atomicAdd(&g_cnt, 1);
        g_ulist[pos] = tok;
        __threadfence();
        g_remap[tok] = pos;
    }
}

// ---------------- kernel P2: rewrite sentence with compact ids --------------
__global__ __launch_bounds__(256) void sentmap_k(const int* __restrict__ sent32) {
    bool is64 = sent_is64(sent32);
    int i = blockIdx.x * 256 + threadIdx.x;
    int tok = is64 ? __ldg(&sent32[2 * i]) : __ldg(&sent32[i]);
    g_sent[i] = g_remap[tok];
}

// ---------------- kernel 0a: convert emb fp32 -> fp16 ------------------------
__global__ __launch_bounds__(256) void conv_emb_k(const float* __restrict__ emb) {
    size_t i = ((size_t)blockIdx.x * 256 + threadIdx.x) * 4;
    if (i >= (size_t)V_ * E_) return;
    float4 x = *(const float4*)(emb + i);
    __half2* o = (__half2*)(g_emb + i);
    o[0] = __floats2half2_rn(x.x, x.y);
    o[1] = __floats2half2_rn(x.z, x.w);
}

// ---------------- kernel 0b: transpose W[e,u] -> Wt[u,e] fp16 ---------------
__global__ __launch_bounds__(256) void transpose_w_k(
    const float* __restrict__ Wf, const float* __restrict__ Wi, const float* __restrict__ Wh) {
    __shared__ float t[32][33];
    int mat = blockIdx.z;
    const float* W = (mat == 0) ? Wf : (mat == 1) ? Wi : Wh;
    int u0 = blockIdx.x * 32, e0 = blockIdx.y * 32;
    int tx = threadIdx.x, ty = threadIdx.y;   // block (32, 8)
    #pragma unroll
    for (int r = 0; r < 32; r += 8)
        t[ty + r][tx] = W[(size_t)(e0 + ty + r) * U_ + u0 + tx];
    __syncthreads();
    __half* oh = g_wt[mat];
    #pragma unroll
    for (int r = 0; r < 32; r += 8)
        oh[(size_t)(u0 + ty + r) * E_ + e0 + tx] = __float2half_rn(t[tx][ty + r]);
}

// ---------------- kernel 1: pipelined fp16 mma triple GEMM + gates ----------
// Rows = compacted unique tokens (gather via g_ulist); blocks past g_cnt exit.
__global__ __launch_bounds__(256, 1) void gates_mma(
    const float* __restrict__ bfb, const float* __restrict__ bib,
    const float* __restrict__ bhb)
{
    const int cnt = g_cnt;
    const int m0 = blockIdx.y * BM;
    if (m0 >= cnt) return;
    const int n0 = blockIdx.x * BN;

    extern __shared__ char smem[];
    __shared__ int srid[BM];
    const uint32_t sb = smem_u32(smem);
    const int tid  = threadIdx.x;
    const int lane = tid & 31, wid = tid >> 5;
    const int wm = wid & 3;          // 4 warps in m
    const int wn = wid >> 2;         // 2 warps in n

    if (tid < BM) {
        int m = m0 + tid;
        srid[tid] = __ldg(&g_ulist[m < cnt ? m : cnt - 1]);
    }
    __syncthreads();

    float acc[3][2][4][4];
    #pragma unroll
    for (int m = 0; m < 3; m++)
        #pragma unroll
        for (int t = 0; t < 2; t++)
            #pragma unroll
            for (int j = 0; j < 4; j++)
                #pragma unroll
                for (int r = 0; r < 4; r++) acc[m][t][j][r] = 0.f;

    // ---- stage loader: 5 cp.async per thread ----
    auto load_stage = [&](int kt, int s) {
        const uint32_t base = sb + s * STAGE_BYTES;
        const int k0 = kt * BK;
        #pragma unroll
        for (int i = 0; i < 2; i++) {                 // A: 512 chunks of 16B
            int c = tid + i * 256;
            int row = c >> 2, seg = c & 3;
            cp16(base + row * (SROW * 2) + seg * 16,
                 g_emb + (size_t)srid[row] * E_ + k0 + seg * 8);
        }
        {                                              // B: 3 tiles x 256 chunks
            int row = tid >> 2, seg = tid & 3;
            uint32_t d = base + A_TILE + row * (SROW * 2) + seg * 16;
            size_t off = (size_t)(n0 + row) * E_ + k0 + seg * 8;
            #pragma unroll
            for (int t = 0; t < 3; t++)
                cp16(d + t * B_TILE, g_wt[t] + off);
        }
        CP_COMMIT();
    };

    const int lq = lane >> 3, lr = lane & 7;

    load_stage(0, 0);
    load_stage(1, 1);
    load_stage(2, 2);

    for (int kt = 0; kt < NKT; ++kt) {
        if      (kt < NKT - 2) { CP_WAIT(2); }
        else if (kt < NKT - 1) { CP_WAIT(1); }
        else                   { CP_WAIT(0); }
        __syncthreads();

        const uint32_t base = sb + (kt % STAGES) * STAGE_BYTES;
        #pragma unroll
        for (int ks = 0; ks < 2; ++ks) {
            uint32_t aF[2][4];
            #pragma unroll
            for (int t = 0; t < 2; t++) {
                int row = wm * 32 + t * 16 + (lq & 1) * 8 + lr;
                ldsm4(aF[t], base + row * (SROW * 2) + ks * 32 + (lq >> 1) * 16);
            }
            #pragma unroll
            for (int mat = 0; mat < 3; mat++) {
                uint32_t bF[2][4];
                #pragma unroll
                for (int jp = 0; jp < 2; jp++) {
                    int row = wn * 32 + jp * 16 + (lq >> 1) * 8 + lr;
                    ldsm4(bF[jp], base + A_TILE + mat * B_TILE
                                + row * (SROW * 2) + ks * 32 + (lq & 1) * 16);
                }
                #pragma unroll
                for (int t = 0; t < 2; t++)
                    #pragma unroll
                    for (int j = 0; j < 4; j++)
                        mma16816(acc[mat][t][j], aF[t], &bF[j >> 1][(j & 1) * 2]);
            }
        }
        __syncthreads();
        if (kt + 3 < NKT) load_stage(kt + 3, (kt + 3) % STAGES);
    }

    // ---- epilogue: gate math, packed half2 (f_n, g) stores ----
    #pragma unroll
    for (int j = 0; j < 4; j++) {
        int col = n0 + wn * 32 + j * 8 + (lane & 3) * 2;
        float2 bfv = *(const float2*)(bfb + col);
        float2 biv = *(const float2*)(bib + col);
        float2 bhv = *(const float2*)(bhb + col);
        #pragma unroll
        for (int t = 0; t < 2; t++) {
            #pragma unroll
            for (int rh = 0; rh < 2; rh++) {
                int row = m0 + wm * 32 + t * 16 + (lane >> 2) + rh * 8;
                if (row >= cnt) continue;
                float zf0 = acc[0][t][j][rh * 2 + 0] + bfv.x;
                float zf1 = acc[0][t][j][rh * 2 + 1] + bfv.y;
                float zi0 = acc[1][t][j][rh * 2 + 0] + biv.x;
                float zi1 = acc[1][t][j][rh * 2 + 1] + biv.y;
                float zh0 = acc[2][t][j][rh * 2 + 0] + bhv.x;
                float zh1 = acc[2][t][j][rh * 2 + 1] + bhv.y;
                float f0 = 1.f / (1.f + __expf(-zf0));
                float f1 = 1.f / (1.f + __expf(-zf1));
                float i0 = 1.f / (1.f + __expf(-zi0));
                float i1 = 1.f / (1.f + __expf(-zi1));
                float v0 = 1.f / (f0 + i0);
                float v1 = 1.f / (f1 + i1);
                __half2 p0 = __floats2half2_rn(f0 * v0, i0 * v0 * zh0);
                __half2 p1 = __floats2half2_rn(f1 * v1, i1 * v1 * zh1);
                *(uint2*)&g_tab[(size_t)row * U_ + col] =
                    make_uint2(*(uint32_t*)&p0, *(uint32_t*)&p1);
            }
        }
    }
}

// ---------------- kernel 2a: chunked scan (parallel over 16 chunks) ---------
__global__ __launch_bounds__(256) void scan_part()
{
    const int u = blockIdx.x * 256 + threadIdx.x;   // grid.x = 4
    const int b = blockIdx.y;
    const int c = blockIdx.z;
    const int* sr = g_sent + b * S_ + c * CHL;

    float P = 1.f, h = 0.f;
    #pragma unroll 4
    for (int t = 0; t < CHL; t++) {
        int rid = __ldg(&sr[t]);
        __half2 v = g_tab[(size_t)rid * U_ + u];
        float2 fg = __half22float2(v);
        h = fmaf(fg.x, h, fg.y);
        P *= fg.x;
    }
    size_t idx = ((size_t)c * B_ + b) * U_ + u;
    g_P[idx] = P;
    g_Q[idx] = h;
}

// ---------------- kernel 2b: combine chunk results ---------------------------
__global__ __launch_bounds__(256) void scan_combine()
{
    int gid = blockIdx.x * 256 + threadIdx.x;   // 0 .. B*U-1
    int b = gid >> 10, u = gid & 1023;
    float h = 0.f;
    #pragma unroll
    for (int c = 0; c < NCH; c++) {
        size_t idx = ((size_t)c * B_ + b) * U_ + u;
        h = fmaf(g_P[idx], h, g_Q[idx]);
    }
    g_h[gid] = h;
}

// ---------------- kernel 3: head ---------------------------------------------
__global__ __launch_bounds__(256) void head_kernel(
    const float* __restrict__ W1, const float* __restrict__ b1,
    const float* __restrict__ W2, const float* __restrict__ b2,
    float* __restrict__ out)
{
    __shared__ float w12[U_];
    __shared__ float red[256];
    const int b = blockIdx.x, tid = threadIdx.x;

    for (int u = tid; u < U_; u += 256) {
        float s = 0.f;
        #pragma unroll
        for (int c = 0; c < 64; c++) s = fmaf(W1[u * 64 + c], W2[c], s);
        w12[u] = s;
    }
    __syncthreads();
    float p = 0.f;
    for (int u = tid; u < U_; u += 256)
        p = fmaf(g_h[(size_t)b * U_ + u], w12[u], p);
    red[tid] = p;
    __syncthreads();
    #pragma unroll
    for (int s = 128; s > 0; s >>= 1) {
        if (tid < s) red[tid] += red[tid + s];
        __syncthreads();
    }
    if (tid == 0) {
        float c = 0.f;
        #pragma unroll
        for (int j = 0; j < 64; j++) c = fmaf(b1[j], W2[j], c);
        out[b] = 1.f / (1.f + expf(-(red[0] + c + b2[0])));
    }
}

// ---------------- host -------------------------------------------------------
extern "C" void kernel_launch(void* const* d_in, const int* in_sizes, int n_in,
                              void* d_out, int out_size)
{
    const int*   sent = (const int*)  d_in[0];
    const float* emb  = (const float*)d_in[1];
    const float* Wf   = (const float*)d_in[2];
    const float* bf   = (const float*)d_in[3];
    const float* Wi   = (const float*)d_in[4];
    const float* bi   = (const float*)d_in[5];
    const float* Wh   = (const float*)d_in[6];
    const float* bh   = (const float*)d_in[7];
    const float* W1   = (const float*)d_in[8];
    const float* b1   = (const float*)d_in[9];
    const float* W2   = (const float*)d_in[10];
    const float* b2   = (const float*)d_in[11];
    float* out = (float*)d_out;

    cudaFuncSetAttribute(gates_mma, cudaFuncAttributeMaxDynamicSharedMemorySize, SMEM_DYN);

    zero_k<<<(V_ + 255) / 256, 256>>>();
    mark_k<<<(B_ * S_) / 256, 256>>>(sent);
    sentmap_k<<<(B_ * S_) / 256, 256>>>(sent);
    conv_emb_k<<<(int)(((size_t)V_ * E_ / 4 + 255) / 256), 256>>>(emb);
    transpose_w_k<<<dim3(U_ / 32, E_ / 32, 3), dim3(32, 8)>>>(Wf, Wi, Wh);
    gates_mma<<<dim3(U_ / BN, V_ / BM), 256, SMEM_DYN>>>(bf, bi, bh);
    scan_part<<<dim3(U_ / 256, B_, NCH), 256>>>();
    scan_combine<<<(B_ * U_) / 256, 256>>>();
    head_kernel<<<B_, 256>>>(W1, b1, W2, b2, out);
}

// round 6
// speedup vs baseline: 5.4355x; 1.1473x over previous
#include <cuda_runtime.h>
#include <cuda_fp16.h>
#include <math.h>
#include <stdint.h>

#define V_ 32000
#define E_ 1024
#define U_ 1024
#define B_ 64
#define S_ 1024

#define BM 64
#define BN 64
#define BK 32
#define NKT (E_ / BK)            // 32 k-tiles
#define SROW 40                  // padded row stride (fp16 elems) = 80 bytes
#define A_TILE (BM * SROW * 2)   // 5120 B
#define B_TILE (BN * SROW * 2)   // 5120 B
#define STAGE_BYTES (A_TILE + 3 * B_TILE)   // 20480 B
#define STAGES 4
#define SMEM_DYN (STAGES * STAGE_BYTES)     // 81920 B -> 2 CTAs/SM

#define NCH 16                   // scan chunks
#define CHL (S_ / NCH)           // 64 timesteps per chunk

// ---------------- device scratch (__device__ globals; no allocs allowed) ----
__device__ int     g_cnt;
__device__ int     g_remap[V_];
__device__ int     g_ulist[V_];
__device__ int     g_sent[B_ * S_];
__device__ __half2 g_tab[(size_t)V_ * U_];   // (f_n, i_n*h~) packed, row = compact id
__device__ float   g_h [B_ * U_];
__device__ float   g_P [NCH * B_ * U_];
__device__ float   g_Q [NCH * B_ * U_];
__device__ __half  g_emb[(size_t)V_ * E_];
__device__ __half  g_wt[3][(size_t)U_ * E_];

// ---------------- asm helpers (base sm_103 ISA only) ------------------------
__device__ __forceinline__ uint32_t smem_u32(const void* p) {
    uint32_t a;
    asm("{ .reg .u64 t; cvta.to.shared.u64 t, %1; cvt.u32.u64 %0, t; }" : "=r"(a) : "l"(p));
    return a;
}
__device__ __forceinline__ void cp16(uint32_t dst, const void* src) {
    asm volatile("cp.async.cg.shared.global [%0], [%1], 16;" :: "r"(dst), "l"(src));
}
#define CP_COMMIT() asm volatile("cp.async.commit_group;" ::: "memory")
#define CP_WAIT(N)  asm volatile("cp.async.wait_group %0;" :: "n"(N) : "memory")

__device__ __forceinline__ void ldsm4(uint32_t* r, uint32_t addr) {
    asm volatile("ldmatrix.sync.aligned.m8n8.x4.shared.b16 {%0,%1,%2,%3}, [%4];"
        : "=r"(r[0]), "=r"(r[1]), "=r"(r[2]), "=r"(r[3]) : "r"(addr));
}
__device__ __forceinline__ void mma16816(float* c, const uint32_t* a, const uint32_t* b) {
    asm volatile(
        "mma.sync.aligned.m16n8k16.row.col.f32.f16.f16.f32 "
        "{%0,%1,%2,%3}, {%4,%5,%6,%7}, {%8,%9}, {%0,%1,%2,%3};"
        : "+f"(c[0]), "+f"(c[1]), "+f"(c[2]), "+f"(c[3])
        : "r"(a[0]), "r"(a[1]), "r"(a[2]), "r"(a[3]), "r"(b[0]), "r"(b[1]));
}
__device__ __forceinline__ bool sent_is64(const int* __restrict__ s) {
    #pragma unroll 4
    for (int j = 0; j < 64; j++)
        if (__ldg(&s[2 * j + 1]) != 0) return false;
    return true;
}

// ---------------- kernel P0: reset remap + counter ---------------------------
__global__ __launch_bounds__(256) void zero_k() {
    int v = blockIdx.x * 256 + threadIdx.x;
    if (v < V_) g_remap[v] = -1;
    if (v == 0) g_cnt = 0;
}

// ---------------- kernel P1: mark unique tokens, build compact list ---------
__global__ __launch_bounds__(256) void mark_k(const int* __restrict__ sent32) {
    bool is64 = sent_is64(sent32);
    int i = blockIdx.x * 256 + threadIdx.x;            // 0 .. B*S-1
    int tok = is64 ? __ldg(&sent32[2 * i]) : __ldg(&sent32[i]);
    int old = atomicCAS(&g_remap[tok], -1, -2);
    if (old == -1) {
        int pos = atomicAdd(&g_cnt, 1);
        g_ulist[pos] = tok;
        __threadfence();
        g_remap[tok] = pos;
    }
}

// ---------------- kernel P2: rewrite sentence with compact ids --------------
__global__ __launch_bounds__(256) void sentmap_k(const int* __restrict__ sent32) {
    bool is64 = sent_is64(sent32);
    int i = blockIdx.x * 256 + threadIdx.x;
    int tok = is64 ? __ldg(&sent32[2 * i]) : __ldg(&sent32[i]);
    while (true) {                       // spin only if mark still in flight (never, given kernel order)
        int r = g_remap[tok];
        if (r >= 0) { g_sent[i] = r; break; }
    }
}

// ---------------- kernel 0a: convert emb fp32 -> fp16 ------------------------
__global__ __launch_bounds__(256) void conv_emb_k(const float* __restrict__ emb) {
    size_t i = ((size_t)blockIdx.x * 256 + threadIdx.x) * 4;
    if (i >= (size_t)V_ * E_) return;
    float4 x = *(const float4*)(emb + i);
    __half2* o = (__half2*)(g_emb + i);
    o[0] = __floats2half2_rn(x.x, x.y);
    o[1] = __floats2half2_rn(x.z, x.w);
}

// ---------------- kernel 0b: transpose W[e,u] -> Wt[u,e] fp16 ---------------
__global__ __launch_bounds__(256) void transpose_w_k(
    const float* __restrict__ Wf, const float* __restrict__ Wi, const float* __restrict__ Wh) {
    __shared__ float t[32][33];
    int mat = blockIdx.z;
    const float* W = (mat == 0) ? Wf : (mat == 1) ? Wi : Wh;
    int u0 = blockIdx.x * 32, e0 = blockIdx.y * 32;
    int tx = threadIdx.x, ty = threadIdx.y;   // block (32, 8)
    #pragma unroll
    for (int r = 0; r < 32; r += 8)
        t[ty + r][tx] = W[(size_t)(e0 + ty + r) * U_ + u0 + tx];
    __syncthreads();
    __half* oh = g_wt[mat];
    #pragma unroll
    for (int r = 0; r < 32; r += 8)
        oh[(size_t)(u0 + ty + r) * E_ + e0 + tx] = __float2half_rn(t[tx][ty + r]);
}

// ---------------- kernel 1: pipelined fp16 mma triple GEMM + gates ----------
// BM=64, BN=64, 8 warps (warp tile 32x16), acc 48 regs -> 2 CTAs/SM ping-pong.
__global__ __launch_bounds__(256, 2) void gates_mma(
    const float* __restrict__ bfb, const float* __restrict__ bib,
    const float* __restrict__ bhb)
{
    const int cnt = g_cnt;
    const int m0 = blockIdx.y * BM;
    if (m0 >= cnt) return;
    const int n0 = blockIdx.x * BN;

    extern __shared__ char smem[];
    __shared__ int srid[BM];
    const uint32_t sb = smem_u32(smem);
    const int tid  = threadIdx.x;
    const int lane = tid & 31, wid = tid >> 5;
    const int wm = wid & 1;          // 2 warps in m  (2*32 = 64)
    const int wn = wid >> 1;         // 4 warps in n  (4*16 = 64)

    if (tid < BM) {
        int m = m0 + tid;
        srid[tid] = __ldg(&g_ulist[m < cnt ? m : cnt - 1]);
    }
    __syncthreads();

    float acc[3][2][2][4];
    #pragma unroll
    for (int m = 0; m < 3; m++)
        #pragma unroll
        for (int t = 0; t < 2; t++)
            #pragma unroll
            for (int j = 0; j < 2; j++)
                #pragma unroll
                for (int r = 0; r < 4; r++) acc[m][t][j][r] = 0.f;

    // ---- stage loader: 4 cp.async per thread ----
    const int ld_row = tid >> 2, ld_seg = tid & 3;
    auto load_stage = [&](int kt, int s) {
        const uint32_t base = sb + s * STAGE_BYTES;
        const int k0 = kt * BK;
        cp16(base + ld_row * (SROW * 2) + ld_seg * 16,
             g_emb + (size_t)srid[ld_row] * E_ + k0 + ld_seg * 8);
        uint32_t d = base + A_TILE + ld_row * (SROW * 2) + ld_seg * 16;
        size_t off = (size_t)(n0 + ld_row) * E_ + k0 + ld_seg * 8;
        #pragma unroll
        for (int t = 0; t < 3; t++)
            cp16(d + t * B_TILE, g_wt[t] + off);
        CP_COMMIT();
    };

    const int lq = lane >> 3, lr = lane & 7;

    load_stage(0, 0);
    load_stage(1, 1);
    load_stage(2, 2);

    for (int kt = 0; kt < NKT; ++kt) {
        if      (kt < NKT - 2) { CP_WAIT(2); }
        else if (kt < NKT - 1) { CP_WAIT(1); }
        else                   { CP_WAIT(0); }
        __syncthreads();

        const uint32_t base = sb + (kt & (STAGES - 1)) * STAGE_BYTES;
        #pragma unroll
        for (int ks = 0; ks < 2; ++ks) {
            uint32_t aF[2][4];
            #pragma unroll
            for (int t = 0; t < 2; t++) {
                int row = wm * 32 + t * 16 + (lq & 1) * 8 + lr;
                ldsm4(aF[t], base + row * (SROW * 2) + ks * 32 + (lq >> 1) * 16);
            }
            #pragma unroll
            for (int mat = 0; mat < 3; mat++) {
                uint32_t bF[4];
                {
                    int row = wn * 16 + (lq >> 1) * 8 + lr;
                    ldsm4(bF, base + A_TILE + mat * B_TILE
                             + row * (SROW * 2) + ks * 32 + (lq & 1) * 16);
                }
                #pragma unroll
                for (int t = 0; t < 2; t++)
                    #pragma unroll
                    for (int j = 0; j < 2; j++)
                        mma16816(acc[mat][t][j], aF[t], &bF[j * 2]);
            }
        }
        __syncthreads();
        if (kt + 3 < NKT) load_stage(kt + 3, (kt + 3) & (STAGES - 1));
    }

    // ---- epilogue: gate math, packed half2 (f_n, g) stores ----
    #pragma unroll
    for (int j = 0; j < 2; j++) {
        int col = n0 + wn * 16 + j * 8 + (lane & 3) * 2;
        float2 bfv = *(const float2*)(bfb + col);
        float2 biv = *(const float2*)(bib + col);
        float2 bhv = *(const float2*)(bhb + col);
        #pragma unroll
        for (int t = 0; t < 2; t++) {
            #pragma unroll
            for (int rh = 0; rh < 2; rh++) {
                int row = m0 + wm * 32 + t * 16 + (lane >> 2) + rh * 8;
                if (row >= cnt) continue;
                float zf0 = acc[0][t][j][rh * 2 + 0] + bfv.x;
                float zf1 = acc[0][t][j][rh * 2 + 1] + bfv.y;
                float zi0 = acc[1][t][j][rh * 2 + 0] + biv.x;
                float zi1 = acc[1][t][j][rh * 2 + 1] + biv.y;
                float zh0 = acc[2][t][j][rh * 2 + 0] + bhv.x;
                float zh1 = acc[2][t][j][rh * 2 + 1] + bhv.y;
                float f0 = 1.f / (1.f + __expf(-zf0));
                float f1 = 1.f / (1.f + __expf(-zf1));
                float i0 = 1.f / (1.f + __expf(-zi0));
                float i1 = 1.f / (1.f + __expf(-zi1));
                float v0 = 1.f / (f0 + i0);
                float v1 = 1.f / (f1 + i1);
                __half2 p0 = __floats2half2_rn(f0 * v0, i0 * v0 * zh0);
                __half2 p1 = __floats2half2_rn(f1 * v1, i1 * v1 * zh1);
                *(uint2*)&g_tab[(size_t)row * U_ + col] =
                    make_uint2(*(uint32_t*)&p0, *(uint32_t*)&p1);
            }
        }
    }
}

// ---------------- kernel 2a: chunked scan (parallel over 16 chunks) ---------
__global__ __launch_bounds__(256) void scan_part()
{
    const int u = blockIdx.x * 256 + threadIdx.x;   // grid.x = 4
    const int b = blockIdx.y;
    const int c = blockIdx.z;
    const int* sr = g_sent + b * S_ + c * CHL;

    float P = 1.f, h = 0.f;
    #pragma unroll 4
    for (int t = 0; t < CHL; t++) {
        int rid = __ldg(&sr[t]);
        __half2 v = g_tab[(size_t)rid * U_ + u];
        float2 fg = __half22float2(v);
        h = fmaf(fg.x, h, fg.y);
        P *= fg.x;
    }
    size_t idx = ((size_t)c * B_ + b) * U_ + u;
    g_P[idx] = P;
    g_Q[idx] = h;
}

// ---------------- kernel 2b: combine chunk results ---------------------------
__global__ __launch_bounds__(256) void scan_combine()
{
    int gid = blockIdx.x * 256 + threadIdx.x;   // 0 .. B*U-1
    int b = gid >> 10, u = gid & 1023;
    float h = 0.f;
    #pragma unroll
    for (int c = 0; c < NCH; c++) {
        size_t idx = ((size_t)c * B_ + b) * U_ + u;
        h = fmaf(g_P[idx], h, g_Q[idx]);
    }
    g_h[gid] = h;
}

// ---------------- kernel 3: head ---------------------------------------------
__global__ __launch_bounds__(256) void head_kernel(
    const float* __restrict__ W1, const float* __restrict__ b1,
    const float* __restrict__ W2, const float* __restrict__ b2,
    float* __restrict__ out)
{
    __shared__ float w12[U_];
    __shared__ float red[256];
    const int b = blockIdx.x, tid = threadIdx.x;

    for (int u = tid; u < U_; u += 256) {
        float s = 0.f;
        #pragma unroll
        for (int c = 0; c < 64; c++) s = fmaf(W1[u * 64 + c], W2[c], s);
        w12[u] = s;
    }
    __syncthreads();
    float p = 0.f;
    for (int u = tid; u < U_; u += 256)
        p = fmaf(g_h[(size_t)b * U_ + u], w12[u], p);
    red[tid] = p;
    __syncthreads();
    #pragma unroll
    for (int s = 128; s > 0; s >>= 1) {
        if (tid < s) red[tid] += red[tid + s];
        __syncthreads();
    }
    if (tid == 0) {
        float c = 0.f;
        #pragma unroll
        for (int j = 0; j < 64; j++) c = fmaf(b1[j], W2[j], c);
        out[b] = 1.f / (1.f + expf(-(red[0] + c + b2[0])));
    }
}

// ---------------- host -------------------------------------------------------
extern "C" void kernel_launch(void* const* d_in, const int* in_sizes, int n_in,
                              void* d_out, int out_size)
{
    const int*   sent = (const int*)  d_in[0];
    const float* emb  = (const float*)d_in[1];
    const float* Wf   = (const float*)d_in[2];
    const float* bf   = (const float*)d_in[3];
    const float* Wi   = (const float*)d_in[4];
    const float* bi   = (const float*)d_in[5];
    const float* Wh   = (const float*)d_in[6];
    const float* bh   = (const float*)d_in[7];
    const float* W1   = (const float*)d_in[8];
    const float* b1   = (const float*)d_in[9];
    const float* W2   = (const float*)d_in[10];
    const float* b2   = (const float*)d_in[11];
    float* out = (float*)d_out;

    cudaFuncSetAttribute(gates_mma, cudaFuncAttributeMaxDynamicSharedMemorySize, SMEM_DYN);

    zero_k<<<(V_ + 255) / 256, 256>>>();
    mark_k<<<(B_ * S_) / 256, 256>>>(sent);
    sentmap_k<<<(B_ * S_) / 256, 256>>>(sent);
    conv_emb_k<<<(int)(((size_t)V_ * E_ / 4 + 255) / 256), 256>>>(emb);
    transpose_w_k<<<dim3(U_ / 32, E_ / 32, 3), dim3(32, 8)>>>(Wf, Wi, Wh);
    gates_mma<<<dim3(U_ / BN, (V_ + BM - 1) / BM), 256, SMEM_DYN>>>(bf, bi, bh);
    scan_part<<<dim3(U_ / 256, B_, NCH), 256>>>();
    scan_combine<<<(B_ * U_) / 256, 256>>>();
    head_kernel<<<B_, 256>>>(W1, b1, W2, b2, out);
}

// round 7
// speedup vs baseline: 5.8808x; 1.0819x over previous
#include <cuda_runtime.h>
#include <cuda_fp16.h>
#include <math.h>
#include <stdint.h>

#define V_ 32000
#define E_ 1024
#define U_ 1024
#define B_ 64
#define S_ 1024

#define BM 64
#define BN 64
#define BK 32
#define NKT (E_ / BK)            // 32 k-tiles
#define SROW 40                  // padded row stride (fp16 elems) = 80 bytes
#define A_TILE (BM * SROW * 2)   // 5120 B
#define B_TILE (BN * SROW * 2)   // 5120 B
#define STAGE_BYTES (A_TILE + 3 * B_TILE)   // 20480 B
#define STAGES 4
#define SMEM_DYN (STAGES * STAGE_BYTES)     // 81920 B -> 2 CTAs/SM

#define NCH 16                   // scan chunks
#define CHL (S_ / NCH)           // 64 timesteps per chunk

// ---------------- device scratch (__device__ globals; no allocs allowed) ----
__device__ int     g_cnt;
__device__ int     g_remap[V_];
__device__ int     g_ulist[V_];
__device__ int     g_sent[B_ * S_];
__device__ __half2 g_tab[(size_t)V_ * U_];   // (f_n, i_n*h~) packed, row = compact id
__device__ float   g_P [NCH * B_ * U_];
__device__ float   g_Q [NCH * B_ * U_];
__device__ __half  g_embc[(size_t)V_ * E_]; // compacted fp16 embedding rows
__device__ __half  g_wt[3][(size_t)U_ * E_];

// ---------------- asm helpers (base sm_103 ISA only) ------------------------
__device__ __forceinline__ uint32_t smem_u32(const void* p) {
    uint32_t a;
    asm("{ .reg .u64 t; cvta.to.shared.u64 t, %1; cvt.u32.u64 %0, t; }" : "=r"(a) : "l"(p));
    return a;
}
__device__ __forceinline__ void cp16(uint32_t dst, const void* src) {
    asm volatile("cp.async.cg.shared.global [%0], [%1], 16;" :: "r"(dst), "l"(src));
}
#define CP_COMMIT() asm volatile("cp.async.commit_group;" ::: "memory")
#define CP_WAIT(N)  asm volatile("cp.async.wait_group %0;" :: "n"(N) : "memory")

__device__ __forceinline__ void ldsm4(uint32_t* r, uint32_t addr) {
    asm volatile("ldmatrix.sync.aligned.m8n8.x4.shared.b16 {%0,%1,%2,%3}, [%4];"
        : "=r"(r[0]), "=r"(r[1]), "=r"(r[2]), "=r"(r[3]) : "r"(addr));
}
__device__ __forceinline__ void mma16816(float* c, const uint32_t* a, const uint32_t* b) {
    asm volatile(
        "mma.sync.aligned.m16n8k16.row.col.f32.f16.f16.f32 "
        "{%0,%1,%2,%3}, {%4,%5,%6,%7}, {%8,%9}, {%0,%1,%2,%3};"
        : "+f"(c[0]), "+f"(c[1]), "+f"(c[2]), "+f"(c[3])
        : "r"(a[0]), "r"(a[1]), "r"(a[2]), "r"(a[3]), "r"(b[0]), "r"(b[1]));
}
__device__ __forceinline__ bool sent_is64(const int* __restrict__ s) {
    #pragma unroll 4
    for (int j = 0; j < 64; j++)
        if (__ldg(&s[2 * j + 1]) != 0) return false;
    return true;
}

// ---------------- kernel P0: reset remap + counter ---------------------------
__global__ __launch_bounds__(256) void zero_k() {
    int v = blockIdx.x * 256 + threadIdx.x;
    if (v < V_) g_remap[v] = -1;
    if (v == 0) g_cnt = 0;
}

// ---------------- kernel P1: mark unique tokens, build compact list ---------
__global__ __launch_bounds__(256) void mark_k(const int* __restrict__ sent32) {
    bool is64 = sent_is64(sent32);
    int i = blockIdx.x * 256 + threadIdx.x;            // 0 .. B*S-1
    int tok = is64 ? __ldg(&sent32[2 * i]) : __ldg(&sent32[i]);
    int old = atomicCAS(&g_remap[tok], -1, -2);
    if (old == -1) {
        int pos = atomicAdd(&g_cnt, 1);
        g_ulist[pos] = tok;
        __threadfence();
        g_remap[tok] = pos;
    }
}

// ---------------- kernel P2: rewrite sentence with compact ids --------------
__global__ __launch_bounds__(256) void sentmap_k(const int* __restrict__ sent32) {
    bool is64 = sent_is64(sent32);
    int i = blockIdx.x * 256 + threadIdx.x;
    int tok = is64 ? __ldg(&sent32[2 * i]) : __ldg(&sent32[i]);
    g_sent[i] = g_remap[tok];
}

// ---------------- kernel 0a: gather+convert emb rows (compact order) --------
// One block per compact row: g_embc[r,:] = fp16(emb[ulist[r],:])
__global__ __launch_bounds__(256) void gather_emb_k(const float* __restrict__ emb) {
    int r = blockIdx.x;
    if (r >= g_cnt) return;
    int tok = __ldg(&g_ulist[r]);
    const float4* src = (const float4*)(emb + (size_t)tok * E_);
    __half2* dst = (__half2*)(g_embc + (size_t)r * E_);
    int t = threadIdx.x;                 // 256 threads x 4 floats = 1024
    float4 x = __ldg(&src[t]);
    dst[2 * t + 0] = __floats2half2_rn(x.x, x.y);
    dst[2 * t + 1] = __floats2half2_rn(x.z, x.w);
}

// ---------------- kernel 0b: transpose W[e,u] -> Wt[u,e] fp16 ---------------
__global__ __launch_bounds__(256) void transpose_w_k(
    const float* __restrict__ Wf, const float* __restrict__ Wi, const float* __restrict__ Wh) {
    __shared__ float t[32][33];
    int mat = blockIdx.z;
    const float* W = (mat == 0) ? Wf : (mat == 1) ? Wi : Wh;
    int u0 = blockIdx.x * 32, e0 = blockIdx.y * 32;
    int tx = threadIdx.x, ty = threadIdx.y;   // block (32, 8)
    #pragma unroll
    for (int r = 0; r < 32; r += 8)
        t[ty + r][tx] = W[(size_t)(e0 + ty + r) * U_ + u0 + tx];
    __syncthreads();
    __half* oh = g_wt[mat];
    #pragma unroll
    for (int r = 0; r < 32; r += 8)
        oh[(size_t)(u0 + ty + r) * E_ + e0 + tx] = __float2half_rn(t[tx][ty + r]);
}

// ---------------- kernel 1: pipelined fp16 mma triple GEMM + gates ----------
// BM=64, BN=64, 8 warps (warp tile 32x16), 2 CTAs/SM ping-pong.
// A rows contiguous (compacted). One barrier per k-tile (write-stage is 3
// ahead mod 4 of read-stage; all reads of it finished before last barrier).
__global__ __launch_bounds__(256, 2) void gates_mma(
    const float* __restrict__ bfb, const float* __restrict__ bib,
    const float* __restrict__ bhb)
{
    const int cnt = g_cnt;
    const int m0 = blockIdx.y * BM;
    if (m0 >= cnt) return;
    const int n0 = blockIdx.x * BN;

    extern __shared__ char smem[];
    const uint32_t sb = smem_u32(smem);
    const int tid  = threadIdx.x;
    const int lane = tid & 31, wid = tid >> 5;
    const int wm = wid & 1;          // 2 warps in m  (2*32 = 64)
    const int wn = wid >> 1;         // 4 warps in n  (4*16 = 64)

    float acc[3][2][2][4];
    #pragma unroll
    for (int m = 0; m < 3; m++)
        #pragma unroll
        for (int t = 0; t < 2; t++)
            #pragma unroll
            for (int j = 0; j < 2; j++)
                #pragma unroll
                for (int r = 0; r < 4; r++) acc[m][t][j][r] = 0.f;

    // ---- stage loader: 4 cp.async per thread (A row clamped to cnt-1) ----
    const int ld_row = tid >> 2, ld_seg = tid & 3;
    const int a_row  = (m0 + ld_row < cnt) ? (m0 + ld_row) : (cnt - 1);
    const __half* a_src = g_embc + (size_t)a_row * E_ + ld_seg * 8;
    const size_t  b_off = (size_t)(n0 + ld_row) * E_ + ld_seg * 8;
    auto load_stage = [&](int kt, int s) {
        const uint32_t base = sb + s * STAGE_BYTES;
        const int k0 = kt * BK;
        cp16(base + ld_row * (SROW * 2) + ld_seg * 16, a_src + k0);
        uint32_t d = base + A_TILE + ld_row * (SROW * 2) + ld_seg * 16;
        #pragma unroll
        for (int t = 0; t < 3; t++)
            cp16(d + t * B_TILE, g_wt[t] + b_off + k0);
        CP_COMMIT();
    };

    const int lq = lane >> 3, lr = lane & 7;

    load_stage(0, 0);
    load_stage(1, 1);
    load_stage(2, 2);

    for (int kt = 0; kt < NKT; ++kt) {
        if      (kt < NKT - 2) { CP_WAIT(2); }
        else if (kt < NKT - 1) { CP_WAIT(1); }
        else                   { CP_WAIT(0); }
        __syncthreads();

        const uint32_t base = sb + (kt & (STAGES - 1)) * STAGE_BYTES;
        #pragma unroll
        for (int ks = 0; ks < 2; ++ks) {
            uint32_t aF[2][4];
            #pragma unroll
            for (int t = 0; t < 2; t++) {
                int row = wm * 32 + t * 16 + (lq & 1) * 8 + lr;
                ldsm4(aF[t], base + row * (SROW * 2) + ks * 32 + (lq >> 1) * 16);
            }
            #pragma unroll
            for (int mat = 0; mat < 3; mat++) {
                uint32_t bF[4];
                {
                    int row = wn * 16 + (lq >> 1) * 8 + lr;
                    ldsm4(bF, base + A_TILE + mat * B_TILE
                             + row * (SROW * 2) + ks * 32 + (lq & 1) * 16);
                }
                #pragma unroll
                for (int t = 0; t < 2; t++)
                    #pragma unroll
                    for (int j = 0; j < 2; j++)
                        mma16816(acc[mat][t][j], aF[t], &bF[j * 2]);
            }
        }
        // no second barrier: next write target (kt+3)&3 == (kt-1)&3 whose
        // readers all completed before this iteration's barrier.
        if (kt + 3 < NKT) load_stage(kt + 3, (kt + 3) & (STAGES - 1));
    }

    // ---- epilogue: gate math, packed half2 (f_n, g) stores ----
    #pragma unroll
    for (int j = 0; j < 2; j++) {
        int col = n0 + wn * 16 + j * 8 + (lane & 3) * 2;
        float2 bfv = *(const float2*)(bfb + col);
        float2 biv = *(const float2*)(bib + col);
        float2 bhv = *(const float2*)(bhb + col);
        #pragma unroll
        for (int t = 0; t < 2; t++) {
            #pragma unroll
            for (int rh = 0; rh < 2; rh++) {
                int row = m0 + wm * 32 + t * 16 + (lane >> 2) + rh * 8;
                if (row >= cnt) continue;
                float zf0 = acc[0][t][j][rh * 2 + 0] + bfv.x;
                float zf1 = acc[0][t][j][rh * 2 + 1] + bfv.y;
                float zi0 = acc[1][t][j][rh * 2 + 0] + biv.x;
                float zi1 = acc[1][t][j][rh * 2 + 1] + biv.y;
                float zh0 = acc[2][t][j][rh * 2 + 0] + bhv.x;
                float zh1 = acc[2][t][j][rh * 2 + 1] + bhv.y;
                float f0 = 1.f / (1.f + __expf(-zf0));
                float f1 = 1.f / (1.f + __expf(-zf1));
                float i0 = 1.f / (1.f + __expf(-zi0));
                float i1 = 1.f / (1.f + __expf(-zi1));
                float v0 = 1.f / (f0 + i0);
                float v1 = 1.f / (f1 + i1);
                __half2 p0 = __floats2half2_rn(f0 * v0, i0 * v0 * zh0);
                __half2 p1 = __floats2half2_rn(f1 * v1, i1 * v1 * zh1);
                *(uint2*)&g_tab[(size_t)row * U_ + col] =
                    make_uint2(*(uint32_t*)&p0, *(uint32_t*)&p1);
            }
        }
    }
}

// ---------------- kernel 2a: chunked scan (parallel over 16 chunks) ---------
__global__ __launch_bounds__(256) void scan_part()
{
    const int u = blockIdx.x * 256 + threadIdx.x;   // grid.x = 4
    const int b = blockIdx.y;
    const int c = blockIdx.z;
    const int* sr = g_sent + b * S_ + c * CHL;

    float P = 1.f, h = 0.f;
    #pragma unroll 4
    for (int t = 0; t < CHL; t++) {
        int rid = __ldg(&sr[t]);
        __half2 v = g_tab[(size_t)rid * U_ + u];
        float2 fg = __half22float2(v);
        h = fmaf(fg.x, h, fg.y);
        P *= fg.x;
    }
    size_t idx = ((size_t)c * B_ + b) * U_ + u;
    g_P[idx] = P;
    g_Q[idx] = h;
}

// ---------------- kernel 3: fused combine + head -----------------------------
__global__ __launch_bounds__(256) void head_kernel(
    const float* __restrict__ W1, const float* __restrict__ b1,
    const float* __restrict__ W2, const float* __restrict__ b2,
    float* __restrict__ out)
{
    __shared__ float w12[U_];
    __shared__ float red[256];
    const int b = blockIdx.x, tid = threadIdx.x;

    for (int u = tid; u < U_; u += 256) {
        float s = 0.f;
        #pragma unroll
        for (int c = 0; c < 64; c++) s = fmaf(W1[u * 64 + c], W2[c], s);
        w12[u] = s;
    }

    float p = 0.f;
    #pragma unroll
    for (int q = 0; q < U_ / 256; q++) {
        int u = q * 256 + tid;
        float h = 0.f;
        #pragma unroll
        for (int c = 0; c < NCH; c++) {
            size_t idx = ((size_t)c * B_ + b) * U_ + u;
            h = fmaf(g_P[idx], h, g_Q[idx]);
        }
        p = fmaf(h, w12[u], p);
    }
    __syncthreads();
    red[tid] = p;
    __syncthreads();
    #pragma unroll
    for (int s = 128; s > 0; s >>= 1) {
        if (tid < s) red[tid] += red[tid + s];
        __syncthreads();
    }
    if (tid == 0) {
        float c = 0.f;
        #pragma unroll
        for (int j = 0; j < 64; j++) c = fmaf(b1[j], W2[j], c);
        out[b] = 1.f / (1.f + expf(-(red[0] + c + b2[0])));
    }
}

// ---------------- host -------------------------------------------------------
extern "C" void kernel_launch(void* const* d_in, const int* in_sizes, int n_in,
                              void* d_out, int out_size)
{
    const int*   sent = (const int*)  d_in[0];
    const float* emb  = (const float*)d_in[1];
    const float* Wf   = (const float*)d_in[2];
    const float* bf   = (const float*)d_in[3];
    const float* Wi   = (const float*)d_in[4];
    const float* bi   = (const float*)d_in[5];
    const float* Wh   = (const float*)d_in[6];
    const float* bh   = (const float*)d_in[7];
    const float* W1   = (const float*)d_in[8];
    const float* b1   = (const float*)d_in[9];
    const float* W2   = (const float*)d_in[10];
    const float* b2   = (const float*)d_in[11];
    float* out = (float*)d_out;

    cudaFuncSetAttribute(gates_mma, cudaFuncAttributeMaxDynamicSharedMemorySize, SMEM_DYN);

    zero_k<<<(V_ + 255) / 256, 256>>>();
    mark_k<<<(B_ * S_) / 256, 256>>>(sent);
    sentmap_k<<<(B_ * S_) / 256, 256>>>(sent);
    gather_emb_k<<<V_, 256>>>(emb);
    transpose_w_k<<<dim3(U_ / 32, E_ / 32, 3), dim3(32, 8)>>>(Wf, Wi, Wh);
    gates_mma<<<dim3(U_ / BN, (V_ + BM - 1) / BM), 256, SMEM_DYN>>>(bf, bi, bh);
    scan_part<<<dim3(U_ / 256, B_, NCH), 256>>>();
    head_kernel<<<B_, 256>>>(W1, b1, W2, b2, out);
}